// round 8
// baseline (speedup 1.0000x reference)
#include <cuda_runtime.h>
#include <math.h>

// ROC-Star pairwise loss, B=256, E=8192, C=19 (shapes derived at runtime).
// SINGLE kernel launch. Grid (chunks, Cn), all blocks co-resident (one wave):
//   * blockIdx.x==0 blocks ("counter" blocks, one per class): count epoch
//     positives (cap), batch positives (npos), sum(y_pred) for class c;
//     publish cap via release flag (cap+1 encoded in the flag word), then
//     fall through to their own chunk-0 loss work.
//   * all blocks: issue global loads up front (overlap count latency),
//     spin on flag, ballot-compact selected epoch elements, pairwise
//     relu^2 vs batch, fixed-order reduce, write partial.
//   * last block by atomic ticket: reduce partials, degenerate handling,
//     mean over classes, write out; reset ticket+flags for graph replay.

#define TPB   256
#define MAXC  32
#define MAXCH 64

__device__ int      d_capflag[MAXC];     // 0 = not ready, else cap+1
__device__ int      d_npos[MAXC];
__device__ float    d_sumyp[MAXC];
__device__ float    d_part[MAXC * MAXCH];
__device__ unsigned d_ticket;            // zero-init; last block resets

__global__ void __launch_bounds__(TPB)
rocstar_kernel(const float* __restrict__ epoch_pred,
               const float* __restrict__ epoch_true,
               const float* __restrict__ rand_pos,
               const float* __restrict__ rand_neg,
               const float* __restrict__ gamma,
               const float* __restrict__ y_pred,
               const float* __restrict__ y_true,
               float* __restrict__ out,
               int Bn, int Cn, int En, int chunks)
{
    int c    = blockIdx.y;
    int tid  = threadIdx.x;
    int lane = tid & 31, w = tid >> 5;
    int j    = blockIdx.x * TPB + tid;

    // ---- issue all global loads up front (max MLP, overlap count) ----
    float g = gamma[c];

    float e = 0.f, rp = 2.f, rn = 2.f;
    bool  etb = false;
    if (j < En) {
        int off = j * Cn + c;
        e   = epoch_pred[off];
        etb = epoch_true[off] >= 0.5f;
        rp  = rand_pos[off];
        rn  = rand_neg[off];
    }

    float apos = 1e30f, aneg = 1e30f;
    if (tid < Bn) {
        float y   = y_pred[tid * Cn + c];
        bool  pos = y_true[tid * Cn + c] >= 0.5f;
        if (pos) apos =  y;
        else     aneg = -y;
    }

    // ---- cap: counter blocks compute+publish; others spin ----
    __shared__ int s_cap;
    if (blockIdx.x == 0) {
        // count epoch positives for class c (strided, 32 indep loads/thread)
        int cnt = 0;
        {
            const float* base = epoch_true + c;
            int nrows = (En + TPB - 1) / TPB;
            #pragma unroll 8
            for (int r = 0; r < nrows; r++) {
                int row = r * TPB + tid;
                if (row < En)
                    cnt += (base[(size_t)row * Cn] >= 0.5f) ? 1 : 0;
            }
        }
        float sy = (tid < Bn && apos < 1e29f) ?  apos : 0.f;   // y of positives
        float syn = (tid < Bn && aneg < 1e29f) ? -aneg : 0.f;  // y of negatives
        float ysum = sy + syn;                                 // y (any)
        int   np = (tid < Bn && apos < 1e29f) ? 1 : 0;
        #pragma unroll
        for (int o = 16; o > 0; o >>= 1) {
            cnt  += __shfl_down_sync(0xffffffffu, cnt,  o);
            np   += __shfl_down_sync(0xffffffffu, np,   o);
            ysum += __shfl_down_sync(0xffffffffu, ysum, o);
        }
        __shared__ int   sw_c[8], sw_n[8];
        __shared__ float sw_s[8];
        if (lane == 0) { sw_c[w] = cnt; sw_n[w] = np; sw_s[w] = ysum; }
        __syncthreads();
        if (tid == 0) {
            int tc = 0, tn = 0; float ts = 0.f;
            #pragma unroll
            for (int k = 0; k < 8; k++) { tc += sw_c[k]; tn += sw_n[k]; ts += sw_s[k]; }
            d_npos[c]  = tn;
            d_sumyp[c] = ts;
            s_cap = tc;
            __threadfence();                       // release npos/sumyp
            *((volatile int*)&d_capflag[c]) = tc + 1;  // publish cap
        }
        __syncthreads();
    } else {
        if (tid == 0) {
            int f;
            while ((f = *((volatile int*)&d_capflag[c])) == 0)
                __nanosleep(40);
            s_cap = f - 1;
        }
        __syncthreads();
    }

    float p = 1000.0f / fmaxf((float)s_cap, 1.0f);

    bool selpos = false, selneg = false;
    float tval;
    if (etb) { selpos = rp < p; tval = g - e; }   // vs batch negs
    else     { selneg = rn < p; tval = e + g; }   // vs batch pos

    // ---- deterministic ballot compaction ----
    __shared__ float s_tn[TPB], s_tp[TPB];
    __shared__ int wcN[8], wcP[8];
    unsigned bn = __ballot_sync(0xffffffffu, selneg);
    unsigned bp = __ballot_sync(0xffffffffu, selpos);
    if (lane == 0) { wcN[w] = __popc(bn); wcP[w] = __popc(bp); }
    __syncthreads();
    int offN = 0, offP = 0, totN = 0, totP = 0;
    #pragma unroll
    for (int k = 0; k < 8; k++) {
        int vn = wcN[k], vp = wcP[k];
        if (k < w) { offN += vn; offP += vp; }
        totN += vn; totP += vp;
    }
    unsigned lmask = (1u << lane) - 1u;
    if (selneg) s_tn[offN + __popc(bn & lmask)] = tval;
    if (selpos) s_tp[offP + __popc(bp & lmask)] = tval;
    __syncthreads();

    // ---- pairwise: thread owns batch element tid ----
    float acc = 0.f;
    #pragma unroll 4
    for (int k = 0; k < totN; k++) {
        float d = s_tn[k] - apos;        // e + g - y
        float r = fmaxf(d, 0.f);
        acc = fmaf(r, r, acc);
    }
    #pragma unroll 4
    for (int k = 0; k < totP; k++) {
        float d = s_tp[k] - aneg;        // y - e + g
        float r = fmaxf(d, 0.f);
        acc = fmaf(r, r, acc);
    }

    // ---- reduce: warp shuffle, then warp 0 over 8 partials ----
    #pragma unroll
    for (int o = 16; o > 0; o >>= 1)
        acc += __shfl_down_sync(0xffffffffu, acc, o);
    __shared__ float wsum[8];
    if (lane == 0) wsum[w] = acc;
    __syncthreads();
    if (w == 0 && lane == 0) {
        float v = 0.f;
        #pragma unroll
        for (int k = 0; k < 8; k++) v += wsum[k];
        d_part[c * MAXCH + blockIdx.x] = v;
    }

    // ---- last-block finalize (deterministic integer ticket) ----
    __threadfence();
    __shared__ unsigned s_isLast;
    if (tid == 0) {
        unsigned total = gridDim.x * gridDim.y;
        unsigned t = atomicAdd(&d_ticket, 1u);
        s_isLast = (t == total - 1) ? 1u : 0u;
    }
    __syncthreads();
    if (!s_isLast) return;
    __threadfence();

    // one block remains: warp w handles classes w, w+8, ... (all L2-hot)
    __shared__ float sres[MAXC];
    for (int cc = w; cc < Cn; cc += 8) {
        float m = 0.f;
        for (int k = lane; k < chunks; k += 32)
            m += d_part[cc * MAXCH + k];
        #pragma unroll
        for (int o = 16; o > 0; o >>= 1)
            m += __shfl_down_sync(0xffffffffu, m, o);
        if (lane == 0) {
            float res = m / 1000.0f;             // m2/MAX_POS + m3/MAX_NEG
            if (isnan(res)) res = 0.f;
            int np = d_npos[cc];
            if (np == 0 || np == Bn) res = d_sumyp[cc] * 1e-8f;
            sres[cc] = res;
        }
    }
    __syncthreads();
    if (w == 0) {
        float r = (lane < Cn) ? sres[lane] : 0.f;
        #pragma unroll
        for (int o = 16; o > 0; o >>= 1)
            r += __shfl_down_sync(0xffffffffu, r, o);
        if (lane == 0) {
            out[0] = r / (float)Cn;
            d_ticket = 0;                        // reset for graph replay
        }
    }
    // reset flags for replay (values would be identical anyway, but clean)
    if (tid < MAXC) d_capflag[tid] = 0;
}

extern "C" void kernel_launch(void* const* d_in, const int* in_sizes, int n_in,
                              void* d_out, int out_size)
{
    const float* y_pred     = (const float*)d_in[0];
    const float* y_true     = (const float*)d_in[1];
    const float* epoch_pred = (const float*)d_in[2];
    const float* epoch_true = (const float*)d_in[3];
    const float* gamma      = (const float*)d_in[4];
    const float* rand_pos   = (const float*)d_in[5];
    const float* rand_neg   = (const float*)d_in[6];

    int Cn = in_sizes[4];            // gamma: [C]
    int Bn = in_sizes[0] / Cn;       // y_pred: [B, C]
    int En = in_sizes[2] / Cn;       // epoch_pred: [E, C]
    int chunks = (En + TPB - 1) / TPB;

    dim3 grid(chunks, Cn);
    rocstar_kernel<<<grid, TPB>>>(epoch_pred, epoch_true, rand_pos, rand_neg,
                                  gamma, y_pred, y_true, (float*)d_out,
                                  Bn, Cn, En, chunks);
}